// round 17
// baseline (speedup 1.0000x reference)
#include <cuda_runtime.h>
#include <cuda_bf16.h>
#include <math.h>
#include <float.h>
#include <stdint.h>

#define MAXN 50000
#define MAXE 800000
#define DMAX 256
#define DEG_CAP 64

// ---------------- static device scratch ----------------
__device__ float g_q[(size_t)MAXN * DMAX];
__device__ float g_k[(size_t)MAXN * DMAX];
__device__ float g_v[(size_t)MAXN * DMAX];
__device__ float g_h1[(size_t)MAXN * DMAX];
__device__ float g_h2[(size_t)MAXN * DMAX];
// dedicated layer-2 q/k/v (d=128) — avoids aliasing with layer-1 buffers
__device__ float g_q2[(size_t)MAXN * 128];
__device__ float g_k2[(size_t)MAXN * 128];
__device__ float g_v2[(size_t)MAXN * 128];
__device__ float g_score[MAXE];
__device__ int g_src[MAXE];
__device__ int g_dst[MAXE];
__device__ int g_ssrc[MAXE];
__device__ int g_deg[MAXN];
__device__ int g_off[MAXN + 1];
__device__ int g_cursor[MAXN];
__device__ int g_part[256];
__device__ int g_is64;
__device__ float g_psum[256];
__device__ unsigned g_pmax[256];

// pre-split bf16 operands
__device__ uint4 g_ah4[(size_t)MAXN * 512 / 8];
__device__ uint4 g_al4[(size_t)MAXN * 512 / 8];
__device__ uint4 g_wh4[81920];
__device__ uint4 g_wl4[81920];
#define WOFF_L2 524288

__device__ __forceinline__ float* sel(int w) {
    switch (w) {
        case 0: return g_q;
        case 1: return g_k;
        case 2: return g_v;
        case 3: return g_h1;
        case 4: return g_h2;
        case 5: return g_q2;
        case 6: return g_k2;
        default: return g_v2;
    }
}

__device__ __forceinline__ unsigned fenc(float f) {
    unsigned u = __float_as_uint(f);
    return (u & 0x80000000u) ? ~u : (u | 0x80000000u);
}
__device__ __forceinline__ float fdec(unsigned u) {
    u = (u & 0x80000000u) ? (u ^ 0x80000000u) : ~u;
    return __uint_as_float(u);
}
#define ENC_NEG_INF 0x007FFFFFu

// ---------------- PTX helpers ----------------
__device__ __forceinline__ uint32_t smem_u32(const void* p) {
    uint32_t a;
    asm("{ .reg .u64 t; cvta.to.shared.u64 t, %1; cvt.u32.u64 %0, t; }" : "=r"(a) : "l"(p));
    return a;
}

__device__ __forceinline__ void ldm_x4(uint32_t& r0, uint32_t& r1, uint32_t& r2, uint32_t& r3,
                                       uint32_t addr) {
    asm volatile("ldmatrix.sync.aligned.m8n8.x4.shared.b16 {%0,%1,%2,%3}, [%4];"
        : "=r"(r0), "=r"(r1), "=r"(r2), "=r"(r3) : "r"(addr));
}

__device__ __forceinline__ void mma_bf16(float* c, const uint32_t* a, const uint32_t* b) {
    asm volatile("mma.sync.aligned.m16n8k16.row.col.f32.bf16.bf16.f32 "
        "{%0,%1,%2,%3}, {%4,%5,%6,%7}, {%8,%9}, {%0,%1,%2,%3};"
        : "+f"(c[0]), "+f"(c[1]), "+f"(c[2]), "+f"(c[3])
        : "r"(a[0]), "r"(a[1]), "r"(a[2]), "r"(a[3]), "r"(b[0]), "r"(b[1]));
}

__device__ __forceinline__ void cp16(uint32_t saddr, const void* gptr, int srcsize) {
    asm volatile("cp.async.ca.shared.global [%0], [%1], 16, %2;"
        :: "r"(saddr), "l"(gptr), "r"(srcsize) : "memory");
}
__device__ __forceinline__ void cp_commit() {
    asm volatile("cp.async.commit_group;" ::: "memory");
}
__device__ __forceinline__ void cp_wait0() {
    asm volatile("cp.async.wait_group 0;" ::: "memory");
}
__device__ __forceinline__ void cp_wait1() {
    asm volatile("cp.async.wait_group 1;" ::: "memory");
}

__device__ __forceinline__ uint32_t pack_bf(float a, float b) {
    __nv_bfloat162 t = __floats2bfloat162_rn(a, b);
    return *(uint32_t*)&t;
}
__device__ __forceinline__ float bf_hi_val(float v, float& lo) {
    __nv_bfloat16 h = __float2bfloat16_rn(v);
    float hf = __bfloat162float(h);
    lo = v - hf;
    return hf;
}

// ---------------- s2: detect + zero + pool init ----------------
__global__ void detect_zero_kernel(const unsigned* __restrict__ ei, int E, int Nn) {
    int i = blockIdx.x * blockDim.x + threadIdx.x;
    if (i < Nn) g_deg[i] = 0;
    if (i < 256) {
        g_psum[i] = 0.f;
        g_pmax[i] = ENC_NEG_INF;
    }
    if (i == 0) {
        int n = E < 64 ? E : 64;
        int is64 = 1;
        for (int j = 0; j < n; j++) {
            if (ei[2 * j + 1] != 0u) { is64 = 0; break; }
        }
        g_is64 = is64;
    }
}

__global__ void convert_kernel(const void* __restrict__ ei, int E) {
    int i = blockIdx.x * blockDim.x + threadIdx.x;
    if (i >= E) return;
    int s, t;
    if (g_is64) {
        const long long* p = (const long long*)ei;
        s = (int)p[i];
        t = (int)p[E + i];
    } else {
        const int* p = (const int*)ei;
        s = p[i];
        t = p[E + i];
    }
    g_src[i] = s;
    g_dst[i] = t;
    atomicAdd(&g_deg[t], 1);
}

// ---------------- main: fused split_a + split_w ----------------
__global__ void fused_split_kernel(
    const float* __restrict__ x, int t4,
    const float* __restrict__ Wq1, const float* __restrict__ Wk1,
    const float* __restrict__ Wv1, const float* __restrict__ Ws1,
    const float* __restrict__ Wq2, const float* __restrict__ Wk2,
    const float* __restrict__ Wv2, const float* __restrict__ Ws2,
    int b1, int b2, int b3) {
    int blk = blockIdx.x;
    int tid = threadIdx.x;

    if (blk < b1) {
        int i = blk * 256 + tid;
        if (i >= t4) return;
        float4 v = ((const float4*)x)[i];
        if (v.x != v.x) v.x = 0.f;
        if (v.y != v.y) v.y = 0.f;
        if (v.z != v.z) v.z = 0.f;
        if (v.w != v.w) v.w = 0.f;
        float lx, ly, lz, lw;
        float hx = bf_hi_val(v.x, lx);
        float hy = bf_hi_val(v.y, ly);
        float hz = bf_hi_val(v.z, lz);
        float hw = bf_hi_val(v.w, lw);
        ((uint2*)g_ah4)[i] = make_uint2(pack_bf(hx, hy), pack_bf(hz, hw));
        ((uint2*)g_al4)[i] = make_uint2(pack_bf(lx, ly), pack_bf(lz, lw));
    } else if (blk < b2) {
        int j = (blk - b1) * 256 + tid;
        int w = j >> 17;
        int i = j & 131071;
        const float* W = (w == 0) ? Wq1 : (w == 1) ? Wk1 : (w == 2) ? Wv1 : Ws1;
        int k = i >> 8, n = i & 255;
        float v = W[i];
        float lo;
        float hi = bf_hi_val(v, lo);
        size_t o = (size_t)w * 131072 + (size_t)n * 512 + k;
        ((__nv_bfloat16*)g_wh4)[o] = __float2bfloat16_rn(hi);
        ((__nv_bfloat16*)g_wl4)[o] = __float2bfloat16_rn(lo);
    } else if (blk < b3) {
        int j = (blk - b2) * 256 + tid;
        int w = j >> 15;
        int i = j & 32767;
        const float* W = (w == 0) ? Wq2 : (w == 1) ? Wk2 : (w == 2) ? Wv2 : Ws2;
        int k = i >> 7, n = i & 127;
        float v = W[i];
        float lo;
        float hi = bf_hi_val(v, lo);
        size_t o = (size_t)WOFF_L2 + (size_t)w * 32768 + (size_t)n * 256 + k;
        ((__nv_bfloat16*)g_wh4)[o] = __float2bfloat16_rn(hi);
        ((__nv_bfloat16*)g_wl4)[o] = __float2bfloat16_rn(lo);
    }
}

// ---------------- scan + permute ----------------
__global__ void part_sum_kernel(int Nn) {
    __shared__ int red[256];
    int t = threadIdx.x;
    int i = blockIdx.x * 256 + t;
    red[t] = (i < Nn) ? g_deg[i] : 0;
    __syncthreads();
    for (int o = 128; o; o >>= 1) {
        if (t < o) red[t] += red[t + o];
        __syncthreads();
    }
    if (t == 0) g_part[blockIdx.x] = red[0];
}

__global__ void part_scan_kernel(int nb, int Nn) {
    __shared__ int s[256];
    int t = threadIdx.x;
    s[t] = (t < nb) ? g_part[t] : 0;
    __syncthreads();
    for (int o = 1; o < 256; o <<= 1) {
        int u = (t >= o) ? s[t - o] : 0;
        __syncthreads();
        s[t] += u;
        __syncthreads();
    }
    g_part[t] = (t > 0) ? s[t - 1] : 0;
    if (t == 255) g_off[Nn] = s[255];
}

__global__ void off_kernel(int Nn) {
    __shared__ int s[256];
    int t = threadIdx.x;
    int i = blockIdx.x * 256 + t;
    int v = (i < Nn) ? g_deg[i] : 0;
    s[t] = v;
    __syncthreads();
    for (int o = 1; o < 256; o <<= 1) {
        int u = (t >= o) ? s[t - o] : 0;
        __syncthreads();
        s[t] += u;
        __syncthreads();
    }
    if (i < Nn) {
        int excl = s[t] - v + g_part[blockIdx.x];
        g_off[i] = excl;
        g_cursor[i] = excl;
    }
}

__global__ void permute_kernel(int E) {
    int i = blockIdx.x * blockDim.x + threadIdx.x;
    if (i >= E) return;
    int t = g_dst[i];
    int pos = atomicAdd(&g_cursor[t], 1);
    g_ssrc[pos] = g_src[i];
}

// ================= bf16 mma.sync GEMM, cp.async pipeline, occ 2 =================
#define OFF_AH 0
#define OFF_AL 10240
#define OFF_BH 20480
#define OFF_BL 30720
#define BUF_SZ 40960
#define GEMM_SMEM (2 * BUF_SZ)

__global__ __launch_bounds__(256, 2)
void gemm_mma_kernel(int wbase, int tileOff,
                     const float* __restrict__ b0, const float* __restrict__ b1,
                     const float* __restrict__ b2, const float* __restrict__ b3,
                     int c0, int c1, int c2, int c3,
                     int M, int K, int Nt) {
    extern __shared__ char smem[];
    const uint32_t sbase = smem_u32(smem);

    const int tid = threadIdx.x;
    const int wid = tid >> 5;
    const int lid = tid & 31;
    const int wm = wid & 1;
    const int wn = wid >> 1;
    const int rowBase = (blockIdx.y + tileOff) * 128;

    const int cbPerW = Nt >> 7;
    const int wsel = blockIdx.x / cbPerW;
    const int colBase = (blockIdx.x - wsel * cbPerW) * 128;

    const __nv_bfloat16* Ah = (const __nv_bfloat16*)g_ah4;
    const __nv_bfloat16* Al = (const __nv_bfloat16*)g_al4;
    const __nv_bfloat16* Wh = (const __nv_bfloat16*)g_wh4 + (size_t)wbase + (size_t)wsel * K * Nt;
    const __nv_bfloat16* Wl = (const __nv_bfloat16*)g_wl4 + (size_t)wbase + (size_t)wsel * K * Nt;

    const float* bias;
    int csel;
    switch (wsel) {
        case 0: bias = b0; csel = c0; break;
        case 1: bias = b1; csel = c1; break;
        case 2: bias = b2; csel = c2; break;
        default: bias = b3; csel = c3; break;
    }
    float* C = sel(csel);

    float acc[4][4][4];
#pragma unroll
    for (int i = 0; i < 4; i++)
#pragma unroll
        for (int j = 0; j < 4; j++)
#pragma unroll
            for (int q = 0; q < 4; q++) acc[i][j][q] = 0.f;

    const int l_row = tid >> 2;
    const int l_kq = tid & 3;
    const int nChunks = K >> 5;

    const int grow0 = rowBase + l_row;
    const int grow1 = rowBase + l_row + 64;
    const int a_ok0 = (grow0 < M) ? 16 : 0;
    const int a_ok1 = (grow1 < M) ? 16 : 0;
    const int n0 = colBase + l_row;
    const int n1 = colBase + l_row + 64;
    const uint32_t soff0 = (uint32_t)(l_row * 80 + l_kq * 16);
    const uint32_t soff1 = soff0 + 64 * 80;

    auto issue = [&](int c, int b) {
        const int k0 = c << 5;
        uint32_t bb = sbase + b * BUF_SZ;
        cp16(bb + OFF_AH + soff0, Ah + (size_t)grow0 * K + k0 + l_kq * 8, a_ok0);
        cp16(bb + OFF_AL + soff0, Al + (size_t)grow0 * K + k0 + l_kq * 8, a_ok0);
        cp16(bb + OFF_AH + soff1, Ah + (size_t)grow1 * K + k0 + l_kq * 8, a_ok1);
        cp16(bb + OFF_AL + soff1, Al + (size_t)grow1 * K + k0 + l_kq * 8, a_ok1);
        cp16(bb + OFF_BH + soff0, Wh + (size_t)n0 * K + k0 + l_kq * 8, 16);
        cp16(bb + OFF_BL + soff0, Wl + (size_t)n0 * K + k0 + l_kq * 8, 16);
        cp16(bb + OFF_BH + soff1, Wh + (size_t)n1 * K + k0 + l_kq * 8, 16);
        cp16(bb + OFF_BL + soff1, Wl + (size_t)n1 * K + k0 + l_kq * 8, 16);
        cp_commit();
    };

    issue(0, 0);

    int buf = 0;
    for (int c = 0; c < nChunks; c++) {
        if (c + 1 < nChunks) {
            issue(c + 1, buf ^ 1);
            cp_wait1();
        } else {
            cp_wait0();
        }
        __syncthreads();

        uint32_t bb = sbase + buf * BUF_SZ;
        const int lr = lid & 15;
        const int lc = lid >> 4;
        uint32_t AHB = bb + OFF_AH, ALB = bb + OFF_AL;
        uint32_t BHB = bb + OFF_BH, BLB = bb + OFF_BL;
#pragma unroll
        for (int ks = 0; ks < 2; ks++) {
            uint32_t koff = (uint32_t)(ks * 32 + lc * 16);
            uint32_t ah[4][4], al[4][4], bh[4][2], bl[4][2];
#pragma unroll
            for (int i = 0; i < 4; i++) {
                uint32_t ro = (uint32_t)((wm * 64 + i * 16 + lr) * 80) + koff;
                ldm_x4(ah[i][0], ah[i][1], ah[i][2], ah[i][3], AHB + ro);
                ldm_x4(al[i][0], al[i][1], al[i][2], al[i][3], ALB + ro);
            }
#pragma unroll
            for (int j2 = 0; j2 < 2; j2++) {
                uint32_t ro = (uint32_t)((wn * 32 + j2 * 16 + lr) * 80) + koff;
                uint32_t r0, r1, r2, r3;
                ldm_x4(r0, r1, r2, r3, BHB + ro);
                bh[j2 * 2 + 0][0] = r0; bh[j2 * 2 + 0][1] = r2;
                bh[j2 * 2 + 1][0] = r1; bh[j2 * 2 + 1][1] = r3;
                ldm_x4(r0, r1, r2, r3, BLB + ro);
                bl[j2 * 2 + 0][0] = r0; bl[j2 * 2 + 0][1] = r2;
                bl[j2 * 2 + 1][0] = r1; bl[j2 * 2 + 1][1] = r3;
            }
#pragma unroll
            for (int i = 0; i < 4; i++)
#pragma unroll
                for (int j = 0; j < 4; j++) {
                    mma_bf16(acc[i][j], ah[i], bh[j]);
                    mma_bf16(acc[i][j], ah[i], bl[j]);
                    mma_bf16(acc[i][j], al[i], bh[j]);
                }
        }
        __syncthreads();
        buf ^= 1;
    }

    const int lr4 = lid >> 2;
    const int lc2 = (lid & 3) * 2;
#pragma unroll
    for (int j = 0; j < 4; j++) {
        int gc = colBase + wn * 32 + j * 8 + lc2;
        float bi0 = bias[gc], bi1 = bias[gc + 1];
#pragma unroll
        for (int i = 0; i < 4; i++) {
            int gr0 = rowBase + wm * 64 + i * 16 + lr4;
            int gr1 = gr0 + 8;
            if (gr0 < M) {
                float2 o = make_float2(acc[i][j][0] + bi0, acc[i][j][1] + bi1);
                *(float2*)(C + (size_t)gr0 * Nt + gc) = o;
            }
            if (gr1 < M) {
                float2 o = make_float2(acc[i][j][2] + bi0, acc[i][j][3] + bi1);
                *(float2*)(C + (size_t)gr1 * Nt + gc) = o;
            }
        }
    }
}

// ================= fused per-node edge kernel (two-pass) + optional pooling =================
// lay=0: read q/k/v from g_q/g_k/g_v (d=256). lay=1: g_q2/g_k2/g_v2 (d=128).
__global__ __launch_bounds__(256)
void edge_fused_kernel(int nodeBase, int nEnd, int d, int h_sel, float inv_sqrt_d,
                       int do_split, int do_pool, int lay) {
    __shared__ float sc[8][DEG_CAP];
    __shared__ float ps[128];
    __shared__ unsigned pm[128];
    int gw = nodeBase + ((blockIdx.x * blockDim.x + threadIdx.x) >> 5);
    int lane = threadIdx.x & 31;
    int wIn = threadIdx.x >> 5;

    if (do_pool && threadIdx.x < 128) {
        ps[threadIdx.x] = 0.f;
        pm[threadIdx.x] = ENC_NEG_INF;
    }

    const float* Qb = lay ? g_q2 : g_q;
    const float* Kb = lay ? g_k2 : g_k;
    const float* Vb = lay ? g_v2 : g_v;

    const int nv = d >> 7;
    float4 h0 = make_float4(0.f, 0.f, 0.f, 0.f);
    bool valid = (gw < nEnd);

    if (valid) {
        int beg = g_off[gw];
        int deg = g_off[gw + 1] - beg;

        float4 a0 = make_float4(0.f, 0.f, 0.f, 0.f);
        float4 a1 = make_float4(0.f, 0.f, 0.f, 0.f);

        if (deg > 0) {
            const float* qr = Qb + (size_t)gw * d;
            float4 q0 = *(const float4*)(qr + lane * 4);
            float4 q1 = make_float4(0.f, 0.f, 0.f, 0.f);
            if (nv > 1) q1 = *(const float4*)(qr + 128 + lane * 4);

            // ---- pass 1: scores + max (2-edge pipelined) ----
            float mx = -FLT_MAX;
            int j = 0;
            for (; j + 1 < deg; j += 2) {
                int s0 = g_ssrc[beg + j];
                int s1 = g_ssrc[beg + j + 1];
                const float* k0p = Kb + (size_t)s0 * d;
                const float* k1p = Kb + (size_t)s1 * d;
                float4 b0 = *(const float4*)(k0p + lane * 4);
                float4 c0 = *(const float4*)(k1p + lane * 4);
                float sa = q0.x * b0.x + q0.y * b0.y + q0.z * b0.z + q0.w * b0.w;
                float sb = q0.x * c0.x + q0.y * c0.y + q0.z * c0.z + q0.w * c0.w;
                if (nv > 1) {
                    float4 b1 = *(const float4*)(k0p + 128 + lane * 4);
                    float4 c1 = *(const float4*)(k1p + 128 + lane * 4);
                    sa += q1.x * b1.x + q1.y * b1.y + q1.z * b1.z + q1.w * b1.w;
                    sb += q1.x * c1.x + q1.y * c1.y + q1.z * c1.z + q1.w * c1.w;
                }
#pragma unroll
                for (int o = 16; o; o >>= 1) {
                    sa += __shfl_xor_sync(0xFFFFFFFFu, sa, o);
                    sb += __shfl_xor_sync(0xFFFFFFFFu, sb, o);
                }
                sa *= inv_sqrt_d;
                sb *= inv_sqrt_d;
                mx = fmaxf(mx, fmaxf(sa, sb));
                if (lane == 0) {
                    if (j < DEG_CAP) sc[wIn][j] = sa; else g_score[beg + j] = sa;
                    if (j + 1 < DEG_CAP) sc[wIn][j + 1] = sb; else g_score[beg + j + 1] = sb;
                }
            }
            if (j < deg) {
                int s = g_ssrc[beg + j];
                const float* kr = Kb + (size_t)s * d;
                float4 b0 = *(const float4*)(kr + lane * 4);
                float sum = q0.x * b0.x + q0.y * b0.y + q0.z * b0.z + q0.w * b0.w;
                if (nv > 1) {
                    float4 b1 = *(const float4*)(kr + 128 + lane * 4);
                    sum += q1.x * b1.x + q1.y * b1.y + q1.z * b1.z + q1.w * b1.w;
                }
#pragma unroll
                for (int o = 16; o; o >>= 1) sum += __shfl_xor_sync(0xFFFFFFFFu, sum, o);
                sum *= inv_sqrt_d;
                mx = fmaxf(mx, sum);
                if (lane == 0) {
                    if (j < DEG_CAP) sc[wIn][j] = sum; else g_score[beg + j] = sum;
                }
            }
            __syncwarp();

            // ---- pass 2: exp + denom ----
            float den = 0.f;
            for (int jj = lane; jj < deg; jj += 32) {
                float v = (jj < DEG_CAP) ? sc[wIn][jj] : g_score[beg + jj];
                float e = __expf(v - mx);
                if (jj < DEG_CAP) sc[wIn][jj] = e;
                else g_score[beg + jj] = e;
                den += e;
            }
#pragma unroll
            for (int o = 16; o; o >>= 1) den += __shfl_xor_sync(0xFFFFFFFFu, den, o);
            float rden = 1.f / den;
            __syncwarp();

            // ---- pass 3: weighted aggregate (4-edge unrolled) ----
            j = 0;
            for (; j + 3 < deg; j += 4) {
                int s0 = g_ssrc[beg + j];
                int s1 = g_ssrc[beg + j + 1];
                int s2 = g_ssrc[beg + j + 2];
                int s3 = g_ssrc[beg + j + 3];
                float e0 = (j < DEG_CAP) ? sc[wIn][j] : g_score[beg + j];
                float e1 = (j + 1 < DEG_CAP) ? sc[wIn][j + 1] : g_score[beg + j + 1];
                float e2 = (j + 2 < DEG_CAP) ? sc[wIn][j + 2] : g_score[beg + j + 2];
                float e3 = (j + 3 < DEG_CAP) ? sc[wIn][j + 3] : g_score[beg + j + 3];
                float al0 = e0 * rden, al1 = e1 * rden, al2 = e2 * rden, al3 = e3 * rden;
                const float* v0p = Vb + (size_t)s0 * d;
                const float* v1p = Vb + (size_t)s1 * d;
                const float* v2p = Vb + (size_t)s2 * d;
                const float* v3p = Vb + (size_t)s3 * d;
                float4 b0 = *(const float4*)(v0p + lane * 4);
                float4 c0 = *(const float4*)(v1p + lane * 4);
                float4 d0 = *(const float4*)(v2p + lane * 4);
                float4 f0 = *(const float4*)(v3p + lane * 4);
                a0.x += al0 * b0.x + al1 * c0.x + al2 * d0.x + al3 * f0.x;
                a0.y += al0 * b0.y + al1 * c0.y + al2 * d0.y + al3 * f0.y;
                a0.z += al0 * b0.z + al1 * c0.z + al2 * d0.z + al3 * f0.z;
                a0.w += al0 * b0.w + al1 * c0.w + al2 * d0.w + al3 * f0.w;
                if (nv > 1) {
                    float4 b1 = *(const float4*)(v0p + 128 + lane * 4);
                    float4 c1 = *(const float4*)(v1p + 128 + lane * 4);
                    float4 d1 = *(const float4*)(v2p + 128 + lane * 4);
                    float4 f1 = *(const float4*)(v3p + 128 + lane * 4);
                    a1.x += al0 * b1.x + al1 * c1.x + al2 * d1.x + al3 * f1.x;
                    a1.y += al0 * b1.y + al1 * c1.y + al2 * d1.y + al3 * f1.y;
                    a1.z += al0 * b1.z + al1 * c1.z + al2 * d1.z + al3 * f1.z;
                    a1.w += al0 * b1.w + al1 * c1.w + al2 * d1.w + al3 * f1.w;
                }
            }
            for (; j < deg; j++) {
                int s = g_ssrc[beg + j];
                float e = (j < DEG_CAP) ? sc[wIn][j] : g_score[beg + j];
                float alpha = e * rden;
                const float* vr = Vb + (size_t)s * d;
                float4 b0 = *(const float4*)(vr + lane * 4);
                a0.x += alpha * b0.x; a0.y += alpha * b0.y;
                a0.z += alpha * b0.z; a0.w += alpha * b0.w;
                if (nv > 1) {
                    float4 b1 = *(const float4*)(vr + 128 + lane * 4);
                    a1.x += alpha * b1.x; a1.y += alpha * b1.y;
                    a1.z += alpha * b1.z; a1.w += alpha * b1.w;
                }
            }
        }

        float* hr = sel(h_sel) + (size_t)gw * d;
        h0 = *(float4*)(hr + lane * 4);
        h0.x += a0.x; h0.y += a0.y; h0.z += a0.z; h0.w += a0.w;
        *(float4*)(hr + lane * 4) = h0;
        float4 h1 = make_float4(0.f, 0.f, 0.f, 0.f);
        if (nv > 1) {
            h1 = *(float4*)(hr + 128 + lane * 4);
            h1.x += a1.x; h1.y += a1.y; h1.z += a1.z; h1.w += a1.w;
            *(float4*)(hr + 128 + lane * 4) = h1;
        }

        if (do_split) {
            __nv_bfloat16* AhP = (__nv_bfloat16*)g_ah4;
            __nv_bfloat16* AlP = (__nv_bfloat16*)g_al4;
            float lx, ly, lz, lw;
            float hx = bf_hi_val(h0.x, lx);
            float hy = bf_hi_val(h0.y, ly);
            float hz = bf_hi_val(h0.z, lz);
            float hw = bf_hi_val(h0.w, lw);
            *(uint2*)(AhP + (size_t)gw * d + lane * 4) = make_uint2(pack_bf(hx, hy), pack_bf(hz, hw));
            *(uint2*)(AlP + (size_t)gw * d + lane * 4) = make_uint2(pack_bf(lx, ly), pack_bf(lz, lw));
            if (nv > 1) {
                float hx1 = bf_hi_val(h1.x, lx);
                float hy1 = bf_hi_val(h1.y, ly);
                float hz1 = bf_hi_val(h1.z, lz);
                float hw1 = bf_hi_val(h1.w, lw);
                *(uint2*)(AhP + (size_t)gw * d + 128 + lane * 4) = make_uint2(pack_bf(hx1, hy1), pack_bf(hz1, hw1));
                *(uint2*)(AlP + (size_t)gw * d + 128 + lane * 4) = make_uint2(pack_bf(lx, ly), pack_bf(lz, lw));
            }
        }
    }

    // ---- fused pooling (layer 2, d=128) ----
    if (do_pool) {
        __syncthreads();
        if (valid) {
            int c = lane * 4;
            atomicAdd(&ps[c + 0], h0.x);
            atomicAdd(&ps[c + 1], h0.y);
            atomicAdd(&ps[c + 2], h0.z);
            atomicAdd(&ps[c + 3], h0.w);
            atomicMax(&pm[c + 0], fenc(h0.x));
            atomicMax(&pm[c + 1], fenc(h0.y));
            atomicMax(&pm[c + 2], fenc(h0.z));
            atomicMax(&pm[c + 3], fenc(h0.w));
        }
        __syncthreads();
        if (threadIdx.x < 128) {
            atomicAdd(&g_psum[threadIdx.x], ps[threadIdx.x]);
            atomicMax(&g_pmax[threadIdx.x], pm[threadIdx.x]);
        }
    }
}

// ---------------- final pooling output ----------------
__global__ void pool_final_kernel(float* __restrict__ out, int M, int d) {
    int c = threadIdx.x;
    if (c < d) {
        out[c] = g_psum[c] / (float)M;
        out[d + c] = fdec(g_pmax[c]);
    }
}

// ---------------- launch ----------------
extern "C" void kernel_launch(void* const* d_in, const int* in_sizes, int n_in,
                              void* d_out, int out_size) {
    const float* x   = (const float*)d_in[0];
    const void*  ei  = d_in[1];
    const float* Wq1 = (const float*)d_in[3];
    const float* bq1 = (const float*)d_in[4];
    const float* Wk1 = (const float*)d_in[5];
    const float* bk1 = (const float*)d_in[6];
    const float* Wv1 = (const float*)d_in[7];
    const float* bv1 = (const float*)d_in[8];
    const float* Ws1 = (const float*)d_in[9];
    const float* bs1 = (const float*)d_in[10];
    const float* Wq2 = (const float*)d_in[11];
    const float* bq2 = (const float*)d_in[12];
    const float* Wk2 = (const float*)d_in[13];
    const float* bk2 = (const float*)d_in[14];
    const float* Wv2 = (const float*)d_in[15];
    const float* bv2 = (const float*)d_in[16];
    const float* Ws2 = (const float*)d_in[17];
    const float* bs2 = (const float*)d_in[18];
    float* out = (float*)d_out;

    const int D_IN = 512, D_HID = 256, D_OUT = 128;
    int Nn = in_sizes[0] / D_IN;
    int E  = in_sizes[2];

    static cudaStream_t s2 = nullptr;
    static cudaEvent_t evFork = nullptr, evJoin = nullptr, evA = nullptr, evB = nullptr;
    if (!s2) {
        cudaFuncSetAttribute(gemm_mma_kernel,
                             cudaFuncAttributeMaxDynamicSharedMemorySize, GEMM_SMEM);
        cudaStreamCreateWithFlags(&s2, cudaStreamNonBlocking);
        cudaEventCreateWithFlags(&evFork, cudaEventDisableTiming);
        cudaEventCreateWithFlags(&evJoin, cudaEventDisableTiming);
        cudaEventCreateWithFlags(&evA, cudaEventDisableTiming);
        cudaEventCreateWithFlags(&evB, cudaEventDisableTiming);
    }

    int nb = (Nn + 255) / 256;
    int t4 = Nn * D_IN / 4;

    // ---- fork: graph-prep chain on s2 ----
    cudaEventRecord(evFork, 0);
    cudaStreamWaitEvent(s2, evFork, 0);
    detect_zero_kernel<<<nb, 256, 0, s2>>>((const unsigned*)ei, E, Nn);
    convert_kernel<<<(E + 255) / 256, 256, 0, s2>>>(ei, E);
    part_sum_kernel<<<nb, 256, 0, s2>>>(Nn);
    part_scan_kernel<<<1, 256, 0, s2>>>(nb, Nn);
    off_kernel<<<nb, 256, 0, s2>>>(Nn);
    permute_kernel<<<(E + 255) / 256, 256, 0, s2>>>(E);
    cudaEventRecord(evJoin, s2);

    // ---- main stream: splits -> layer-1 GEMM ----
    {
        int bA = (t4 + 255) / 256;
        int bW1 = (4 * D_IN * D_HID) / 256;
        int bW2 = (4 * D_HID * D_OUT) / 256;
        int b1 = bA, b2 = b1 + bW1, b3 = b2 + bW2;
        fused_split_kernel<<<b3, 256>>>(x, t4,
                                        Wq1, Wk1, Wv1, Ws1, Wq2, Wk2, Wv2, Ws2,
                                        b1, b2, b3);
    }

    int nTiles = (Nn + 127) / 128;
    float inv1 = (float)(1.0 / sqrt((double)D_HID));
    float inv2 = (float)(1.0 / sqrt((double)D_OUT));

    {
        dim3 g(8, nTiles);
        gemm_mma_kernel<<<g, 256, GEMM_SMEM>>>(
            0, 0, bq1, bk1, bv1, bs1, 0, 1, 2, 3, Nn, D_IN, D_HID);
    }

    // ---- pipelined edge1 / GEMM2 (layer-2 q/k/v in dedicated buffers) ----
    int tilesA = (nTiles + 1) / 2;
    int Nh = tilesA * 128;
    if (Nh > Nn) Nh = Nn;
    int tilesB = nTiles - tilesA;
    int blksA = (Nh * 32 + 255) / 256;
    int blksB = ((Nn - Nh) * 32 + 255) / 256;

    // edge1_A on main stream (needs GEMM1 + CSR)
    cudaStreamWaitEvent(0, evJoin, 0);
    edge_fused_kernel<<<blksA, 256>>>(0, Nh, D_HID, 3, inv1, 1, 0, 0);
    cudaEventRecord(evA, 0);

    // edge1_B on s2 after edge1_A (so GEMM2_A overlaps with it)
    cudaStreamWaitEvent(s2, evA, 0);
    edge_fused_kernel<<<blksB, 256, 0, s2>>>(Nh, Nn, D_HID, 3, inv1, 1, 0, 0);
    cudaEventRecord(evB, s2);

    // GEMM2_A (rows [0, Nh)) writes g_q2/g_k2/g_v2/g_h2 — no overlap with edge1_B's reads
    {
        dim3 g(4, tilesA);
        gemm_mma_kernel<<<g, 256, GEMM_SMEM>>>(
            WOFF_L2, 0, bq2, bk2, bv2, bs2, 5, 6, 7, 4, Nn, D_HID, D_OUT);
    }
    // GEMM2_B after edge1_B
    cudaStreamWaitEvent(0, evB, 0);
    if (tilesB > 0) {
        dim3 g(4, tilesB);
        gemm_mma_kernel<<<g, 256, GEMM_SMEM>>>(
            WOFF_L2, tilesA, bq2, bk2, bv2, bs2, 5, 6, 7, 4, Nn, D_HID, D_OUT);
    }

    // ===== layer-2 edge + fused pooling (reads g_q2/g_k2/g_v2) =====
    {
        int blks = (Nn * 32 + 255) / 256;
        edge_fused_kernel<<<blks, 256>>>(0, Nn, D_OUT, 4, inv2, 0, 1, 1);
    }

    pool_final_kernel<<<1, 256>>>(out, Nn, D_OUT);
}